// round 13
// baseline (speedup 1.0000x reference)
#include <cuda_runtime.h>
#include <cuda_fp16.h>
#include <math.h>

#define BATCH 2
#define CIN 256
#define NHEADS 8
#define HDIM 32
#define NPIX 4096
#define EPSV 1e-4f
#define NBH (BATCH * NHEADS)
#define NSPLIT 4
#define KT_PER_SPLIT 16
#define PSCL 0.015625f     // 2^-6 partial scale; cancels exactly in sum(O)/sum(l)

#define PADK 40
#define PADV 72
#define PADX 66
#define QSCF (0.17677669529663687f * 1.4426950408889634f)   // 1/sqrt(32) * log2(e)

// ---------------- device scratch ----------------
__device__ __half g_wqkvh[768 * CIN];
__device__ __half g_wouth[CIN * CIN];
__device__ __half g_qh[NBH * NPIX * HDIM];
__device__ __half g_kh[NBH * NPIX * HDIM];
__device__ __half g_vt[NBH * HDIM * NPIX];
__device__ __half g_yh[BATCH * NPIX * CIN];
__device__ __half g_opart[NSPLIT * NBH * NPIX * HDIM];   // unnormalized O partials * 2^-6 (fp16)
__device__ float  g_lpart[NSPLIT * NBH * NPIX];          // l partials * 2^-6 (fp32)

// ---------------- helpers ----------------
__device__ __forceinline__ void mma16816(float c[4],
                                         unsigned a0, unsigned a1, unsigned a2, unsigned a3,
                                         unsigned b0, unsigned b1) {
    asm volatile(
        "mma.sync.aligned.m16n8k16.row.col.f32.f16.f16.f32 "
        "{%0,%1,%2,%3}, {%4,%5,%6,%7}, {%8,%9}, {%0,%1,%2,%3};"
        : "+f"(c[0]), "+f"(c[1]), "+f"(c[2]), "+f"(c[3])
        : "r"(a0), "r"(a1), "r"(a2), "r"(a3), "r"(b0), "r"(b1));
}

__device__ __forceinline__ void mma16816_f16(unsigned& c0, unsigned& c1,
                                             unsigned a0, unsigned a1, unsigned a2, unsigned a3,
                                             unsigned b0, unsigned b1) {
    asm volatile(
        "mma.sync.aligned.m16n8k16.row.col.f16.f16.f16.f16 "
        "{%0,%1}, {%2,%3,%4,%5}, {%6,%7}, {%0,%1};"
        : "+r"(c0), "+r"(c1)
        : "r"(a0), "r"(a1), "r"(a2), "r"(a3), "r"(b0), "r"(b1));
}

__device__ __forceinline__ unsigned h2exp2(unsigned a) {
    unsigned d;
    asm("ex2.approx.f16x2 %0, %1;" : "=r"(d) : "r"(a));
    return d;
}

__device__ __forceinline__ void ldsm4(unsigned& r0, unsigned& r1, unsigned& r2, unsigned& r3,
                                      unsigned addr) {
    asm volatile("ldmatrix.sync.aligned.m8n8.x4.shared.b16 {%0,%1,%2,%3}, [%4];"
                 : "=r"(r0), "=r"(r1), "=r"(r2), "=r"(r3) : "r"(addr));
}

__device__ __forceinline__ void cpa16(unsigned smem_addr, const void* gptr) {
    asm volatile("cp.async.cg.shared.global [%0], [%1], 16;"
                 :: "r"(smem_addr), "l"(__cvta_generic_to_global(gptr)));
}
__device__ __forceinline__ void cpa_commit() {
    asm volatile("cp.async.commit_group;");
}
__device__ __forceinline__ void cpa_wait0() {
    asm volatile("cp.async.wait_group 0;");
}

// ---------------- kernel 1: weight norm -> fp16 (both weights, one launch) ----------------
__global__ void wnorm_kernel(const float* __restrict__ wqkv, const float* __restrict__ wout) {
    const int r = blockIdx.x;                   // 0..1023
    const int t = threadIdx.x;
    const float* wsrc = (r < 768) ? (wqkv + r * CIN) : (wout + (r - 768) * CIN);
    __half* o = (r < 768) ? (g_wqkvh + r * CIN) : (g_wouth + (r - 768) * CIN);
    float v = wsrc[t];
    __shared__ float red[256];
    red[t] = v * v;
    __syncthreads();
    #pragma unroll
    for (int s = 128; s > 0; s >>= 1) {
        if (t < s) red[t] += red[t + s];
        __syncthreads();
    }
    float n = sqrtf(red[0]);
    float scale = 0.0625f / (EPSV + 0.0625f * n);
    o[t] = __float2half_rn(v * scale);
}

// ---------------- kernel 2: fused QKV HMMA GEMM + pixel-norm ----------------
// Block: 64 pixels x 128 channels, 8 warps (2 pix-groups x 4 ch-groups).
// Warp = 32 pixels x 32 channels (one head-chunk). K=256.
__global__ void __launch_bounds__(256) qkv_fused_kernel(const float* __restrict__ x) {
    const int px0 = blockIdx.x * 64;
    const int by  = blockIdx.y;
    const int b   = blockIdx.z;
    const int sec = by >> 1;
    const int cofs = (by & 1) * 128;

    const int tid = threadIdx.x;
    const int w = tid >> 5, lane = tid & 31;
    const int lq = lane >> 2, lr = lane & 3;
    const int wm = w & 1, wn = w >> 1;

    __shared__ __half sX[64 * PADX];
    __shared__ __half sW[128 * 72];

    float acc[2][4][4];
    #pragma unroll
    for (int i = 0; i < 2; ++i)
        #pragma unroll
        for (int j = 0; j < 4; ++j)
            #pragma unroll
            for (int q = 0; q < 4; ++q) acc[i][j][q] = 0.f;

    const float* Xg = x + (size_t)b * CIN * NPIX + px0;
    const __half* Wg = g_wqkvh + (size_t)(sec * 256 + cofs) * CIN;

    for (int kc = 0; kc < 4; ++kc) {
        __syncthreads();
        // x tile transpose: 64px x 64ch -> sX[pix][c]
        #pragma unroll
        for (int i = 0; i < 4; ++i) {
            int fidx = tid + i * 256;          // 0..1023
            int pix = fidx & 63;
            int c0 = (fidx >> 6) * 4;          // 0..60
            const float* src = Xg + (size_t)(kc * 64 + c0) * NPIX + pix;
            float v0 = src[0];
            float v1 = src[NPIX];
            float v2 = src[2 * NPIX];
            float v3 = src[3 * NPIX];
            *(__half2*)&sX[pix * PADX + c0]     = __floats2half2_rn(v0, v1);
            *(__half2*)&sX[pix * PADX + c0 + 2] = __floats2half2_rn(v2, v3);
        }
        #pragma unroll
        for (int i = tid; i < 1024; i += 256) {
            int n = i >> 3, seg = i & 7;
            *(uint4*)&sW[n * 72 + seg * 8] =
                *(const uint4*)(Wg + (size_t)n * CIN + kc * 64 + seg * 8);
        }
        __syncthreads();

        #pragma unroll
        for (int ks = 0; ks < 4; ++ks) {
            int kk0 = ks * 16;
            unsigned a[2][4];
            #pragma unroll
            for (int mt = 0; mt < 2; ++mt) {
                int am = wm * 32 + mt * 16;
                a[mt][0] = *(unsigned*)&sX[(am + lq) * PADX + kk0 + lr * 2];
                a[mt][1] = *(unsigned*)&sX[(am + lq + 8) * PADX + kk0 + lr * 2];
                a[mt][2] = *(unsigned*)&sX[(am + lq) * PADX + kk0 + lr * 2 + 8];
                a[mt][3] = *(unsigned*)&sX[(am + lq + 8) * PADX + kk0 + lr * 2 + 8];
            }
            #pragma unroll
            for (int nt = 0; nt < 4; ++nt) {
                int n = wn * 32 + nt * 8 + lq;
                unsigned b0 = *(unsigned*)&sW[n * 72 + kk0 + lr * 2];
                unsigned b1 = *(unsigned*)&sW[n * 72 + kk0 + lr * 2 + 8];
                #pragma unroll
                for (int mt = 0; mt < 2; ++mt)
                    mma16816(acc[mt][nt], a[mt][0], a[mt][1], a[mt][2], a[mt][3], b0, b1);
            }
        }
    }

    // ---- epilogue: per-pixel RMS over this warp's 32-channel chunk ----
    #pragma unroll
    for (int mt = 0; mt < 2; ++mt) {
        float ss0 = 0.f, ss1 = 0.f;
        #pragma unroll
        for (int nt = 0; nt < 4; ++nt) {
            ss0 += acc[mt][nt][0] * acc[mt][nt][0] + acc[mt][nt][1] * acc[mt][nt][1];
            ss1 += acc[mt][nt][2] * acc[mt][nt][2] + acc[mt][nt][3] * acc[mt][nt][3];
        }
        ss0 += __shfl_xor_sync(0xffffffffu, ss0, 1);
        ss0 += __shfl_xor_sync(0xffffffffu, ss0, 2);
        ss1 += __shfl_xor_sync(0xffffffffu, ss1, 1);
        ss1 += __shfl_xor_sync(0xffffffffu, ss1, 2);
        float sc0 = rsqrtf(ss0 * (1.0f / 32.0f) + EPSV);
        float sc1 = rsqrtf(ss1 * (1.0f / 32.0f) + EPSV);
        if (sec == 0) { sc0 *= QSCF; sc1 *= QSCF; }

        int hh = (cofs >> 5) + wn;
        int bh = b * NHEADS + hh;
        int pix0r = px0 + wm * 32 + mt * 16 + lq;
        int pix1r = pix0r + 8;

        if (sec == 2) {
            #pragma unroll
            for (int nt = 0; nt < 4; ++nt) {
                int d = nt * 8 + lr * 2;
                __half* base = g_vt + (size_t)bh * HDIM * NPIX;
                base[(size_t)(d)     * NPIX + pix0r] = __float2half_rn(acc[mt][nt][0] * sc0);
                base[(size_t)(d + 1) * NPIX + pix0r] = __float2half_rn(acc[mt][nt][1] * sc0);
                base[(size_t)(d)     * NPIX + pix1r] = __float2half_rn(acc[mt][nt][2] * sc1);
                base[(size_t)(d + 1) * NPIX + pix1r] = __float2half_rn(acc[mt][nt][3] * sc1);
            }
        } else {
            __half* dst = (sec == 0) ? g_qh : g_kh;
            __half* r0p = dst + ((size_t)bh * NPIX + pix0r) * HDIM;
            __half* r1p = dst + ((size_t)bh * NPIX + pix1r) * HDIM;
            #pragma unroll
            for (int nt = 0; nt < 4; ++nt) {
                int d = nt * 8 + lr * 2;
                *(__half2*)(r0p + d) = __floats2half2_rn(acc[mt][nt][0] * sc0,
                                                         acc[mt][nt][1] * sc0);
                *(__half2*)(r1p + d) = __floats2half2_rn(acc[mt][nt][2] * sc1,
                                                         acc[mt][nt][3] * sc1);
            }
        }
    }
}

// ---------------- kernel 3: flash attention, split-KV (R12 core, unchanged) ----------------
__global__ void __launch_bounds__(128, 4) attn_mma_kernel() {
    const int qb = blockIdx.x;
    const int bh = blockIdx.y;
    const int sp = blockIdx.z;
    const int tid = threadIdx.x;
    const int w = tid >> 5, lane = tid & 31;
    const int lq = lane >> 2, lr = lane & 3;

    const __half* Qg = g_qh + ((size_t)bh * NPIX + qb * 128) * HDIM;
    const __half* Kg = g_kh + ((size_t)bh * NPIX + sp * (KT_PER_SPLIT * 64)) * HDIM;
    const __half* Vg = g_vt + (size_t)bh * HDIM * NPIX + sp * (KT_PER_SPLIT * 64);

    __shared__ __half sQ[128 * PADK];
    __shared__ __half sK[2][64 * PADK];
    __shared__ __half sVt[2][32 * PADV];

    const unsigned sq_u32 = (unsigned)__cvta_generic_to_shared(&sQ[0]);
    const unsigned kbase0 = (unsigned)__cvta_generic_to_shared(&sK[0][0]);
    const unsigned vbase0 = (unsigned)__cvta_generic_to_shared(&sVt[0][0]);
    const unsigned KBUF = 64 * PADK * 2;
    const unsigned VBUF = 32 * PADV * 2;

    #pragma unroll
    for (int i = 0; i < 4; ++i) {
        int idx = tid + i * 128;
        int row = idx >> 2, seg = idx & 3;
        cpa16(sq_u32 + (row * PADK + seg * 8) * 2, Qg + row * 32 + seg * 8);
    }
    #pragma unroll
    for (int i = 0; i < 2; ++i) {
        int s = tid + i * 128;
        int kr = s >> 2, ksg = s & 3;
        cpa16(kbase0 + (kr * PADK + ksg * 8) * 2, Kg + (size_t)kr * 32 + ksg * 8);
        int vr = s >> 3, vsg = s & 7;
        cpa16(vbase0 + (vr * PADV + vsg * 8) * 2, Vg + (size_t)vr * NPIX + vsg * 8);
    }
    cpa_commit();
    cpa_wait0();
    __syncthreads();

    unsigned qf[2][2][4];
    #pragma unroll
    for (int mt = 0; mt < 2; ++mt) {
        int r0 = w * 32 + mt * 16 + lq;
        int r1 = r0 + 8;
        #pragma unroll
        for (int ks = 0; ks < 2; ++ks) {
            qf[mt][ks][0] = *(unsigned*)&sQ[r0 * PADK + ks * 16 + lr * 2];
            qf[mt][ks][1] = *(unsigned*)&sQ[r1 * PADK + ks * 16 + lr * 2];
            qf[mt][ks][2] = *(unsigned*)&sQ[r0 * PADK + ks * 16 + lr * 2 + 8];
            qf[mt][ks][3] = *(unsigned*)&sQ[r1 * PADK + ks * 16 + lr * 2 + 8];
        }
    }

    const unsigned klane = ((lane & 7) * PADK + (lane >> 3) * 8) * 2;
    const unsigned vlane = ((lane & 7) * PADV + (lane >> 3) * 8) * 2;

    float lsum[2][2];
    lsum[0][0] = lsum[0][1] = lsum[1][0] = lsum[1][1] = 0.f;
    float of[2][4][4];
    #pragma unroll
    for (int mt = 0; mt < 2; ++mt)
        #pragma unroll
        for (int nt = 0; nt < 4; ++nt)
            #pragma unroll
            for (int q = 0; q < 4; ++q) of[mt][nt][q] = 0.f;

    for (int kt = 0; kt < KT_PER_SPLIT; ++kt) {
        const int cur = kt & 1;
        const unsigned kb_u32 = kbase0 + cur * KBUF;
        const unsigned vb_u32 = vbase0 + cur * VBUF;

        if (kt < KT_PER_SPLIT - 1) {
            const unsigned kb_n = kbase0 + (cur ^ 1) * KBUF;
            const unsigned vb_n = vbase0 + (cur ^ 1) * VBUF;
            #pragma unroll
            for (int i = 0; i < 2; ++i) {
                int s = tid + i * 128;
                int kr = s >> 2, ksg = s & 3;
                cpa16(kb_n + (kr * PADK + ksg * 8) * 2,
                      Kg + (size_t)((kt + 1) * 64 + kr) * 32 + ksg * 8);
                int vr = s >> 3, vsg = s & 7;
                cpa16(vb_n + (vr * PADV + vsg * 8) * 2,
                      Vg + (size_t)vr * NPIX + (kt + 1) * 64 + vsg * 8);
            }
        }
        cpa_commit();

        unsigned s01[2][8], s23[2][8];
        #pragma unroll
        for (int j = 0; j < 8; ++j) {
            s01[0][j] = s23[0][j] = 0u;
            s01[1][j] = s23[1][j] = 0u;
        }
        #pragma unroll
        for (int j = 0; j < 8; ++j) {
            unsigned kb0, kb1, kb2, kb3;
            ldsm4(kb0, kb1, kb2, kb3, kb_u32 + j * (8 * PADK * 2) + klane);
            mma16816_f16(s01[0][j], s23[0][j], qf[0][0][0], qf[0][0][1], qf[0][0][2], qf[0][0][3], kb0, kb1);
            mma16816_f16(s01[0][j], s23[0][j], qf[0][1][0], qf[0][1][1], qf[0][1][2], qf[0][1][3], kb2, kb3);
            mma16816_f16(s01[1][j], s23[1][j], qf[1][0][0], qf[1][0][1], qf[1][0][2], qf[1][0][3], kb0, kb1);
            mma16816_f16(s01[1][j], s23[1][j], qf[1][1][0], qf[1][1][1], qf[1][1][2], qf[1][1][3], kb2, kb3);
        }

        #pragma unroll
        for (int mt = 0; mt < 2; ++mt) {
            __half2 acc01 = __floats2half2_rn(0.f, 0.f);
            __half2 acc23 = __floats2half2_rn(0.f, 0.f);
            #pragma unroll
            for (int j = 0; j < 8; ++j) {
                s01[mt][j] = h2exp2(s01[mt][j]);
                s23[mt][j] = h2exp2(s23[mt][j]);
                acc01 = __hadd2(acc01, *(__half2*)&s01[mt][j]);
                acc23 = __hadd2(acc23, *(__half2*)&s23[mt][j]);
            }
            lsum[mt][0] += __low2float(acc01) + __high2float(acc01);
            lsum[mt][1] += __low2float(acc23) + __high2float(acc23);
        }

        #pragma unroll
        for (int nt = 0; nt < 4; ++nt) {
            unsigned va0, va1, va2, va3, vb0, vb1, vb2, vb3;
            ldsm4(va0, va1, va2, va3, vb_u32 + nt * (8 * PADV * 2) + vlane);
            ldsm4(vb0, vb1, vb2, vb3, vb_u32 + nt * (8 * PADV * 2) + 64 + vlane);
            #pragma unroll
            for (int mt = 0; mt < 2; ++mt) {
                unsigned od0 = 0u, od1 = 0u;
                mma16816_f16(od0, od1, s01[mt][0], s23[mt][0], s01[mt][1], s23[mt][1], va0, va1);
                mma16816_f16(od0, od1, s01[mt][2], s23[mt][2], s01[mt][3], s23[mt][3], va2, va3);
                mma16816_f16(od0, od1, s01[mt][4], s23[mt][4], s01[mt][5], s23[mt][5], vb0, vb1);
                mma16816_f16(od0, od1, s01[mt][6], s23[mt][6], s01[mt][7], s23[mt][7], vb2, vb3);
                float2 f0 = __half22float2(*(__half2*)&od0);
                float2 f1 = __half22float2(*(__half2*)&od1);
                of[mt][nt][0] += f0.x; of[mt][nt][1] += f0.y;
                of[mt][nt][2] += f1.x; of[mt][nt][3] += f1.y;
            }
        }

        cpa_wait0();
        __syncthreads();
    }

    __half* Obase = g_opart + ((size_t)(sp * NBH + bh) * NPIX + qb * 128) * HDIM;
    float* Lbase = g_lpart + (size_t)(sp * NBH + bh) * NPIX + qb * 128;
    #pragma unroll
    for (int mt = 0; mt < 2; ++mt) {
        float l0 = lsum[mt][0], l1 = lsum[mt][1];
        l0 += __shfl_xor_sync(0xffffffffu, l0, 1);
        l0 += __shfl_xor_sync(0xffffffffu, l0, 2);
        l1 += __shfl_xor_sync(0xffffffffu, l1, 1);
        l1 += __shfl_xor_sync(0xffffffffu, l1, 2);

        int r0 = w * 32 + mt * 16 + lq;
        int r1 = r0 + 8;
        if (lr == 0) {
            Lbase[r0] = l0 * PSCL;
            Lbase[r1] = l1 * PSCL;
        }
        #pragma unroll
        for (int nt = 0; nt < 4; ++nt) {
            int col = nt * 8 + lr * 2;
            *(__half2*)(Obase + (size_t)r0 * HDIM + col) =
                __floats2half2_rn(of[mt][nt][0] * PSCL, of[mt][nt][1] * PSCL);
            *(__half2*)(Obase + (size_t)r1 * HDIM + col) =
                __floats2half2_rn(of[mt][nt][2] * PSCL, of[mt][nt][3] * PSCL);
        }
    }
}

// ---------------- kernel 3b: combine split partials -> g_yh ----------------
__global__ void __launch_bounds__(256) attn_combine_kernel() {
    int t = blockIdx.x * 256 + threadIdx.x;     // 0..131071
    int half_id = t & 1;
    int pix = (t >> 1) & (NPIX - 1);
    int bh = t >> 13;
    int b = bh >> 3, h = bh & 7;
    int dofs = half_id * 16;

    float l = 0.f;
    #pragma unroll
    for (int sp = 0; sp < NSPLIT; ++sp)
        l += g_lpart[(size_t)(sp * NBH + bh) * NPIX + pix];
    float inv = 1.0f / l;

    __half* dst = g_yh + ((size_t)b * NPIX + pix) * CIN + h * 32 + dofs;

    #pragma unroll
    for (int g = 0; g < 2; ++g) {
        float a[8] = {0.f, 0.f, 0.f, 0.f, 0.f, 0.f, 0.f, 0.f};
        #pragma unroll
        for (int sp = 0; sp < NSPLIT; ++sp) {
            const __half* o = g_opart + ((size_t)(sp * NBH + bh) * NPIX + pix) * HDIM + dofs + g * 8;
            uint4 v = *(const uint4*)o;
            const __half2* h2 = (const __half2*)&v;
            #pragma unroll
            for (int q = 0; q < 4; ++q) {
                float2 f = __half22float2(h2[q]);
                a[q * 2]     += f.x;
                a[q * 2 + 1] += f.y;
            }
        }
        __half2 outv[4];
        #pragma unroll
        for (int q = 0; q < 4; ++q)
            outv[q] = __floats2half2_rn(a[q * 2] * inv, a[q * 2 + 1] * inv);
        *(uint4*)(dst + g * 8) = *(uint4*)outv;
    }
}

// ---------------- kernel 4: out GEMM HMMA + mp_add ----------------
// Block: 128 channels x 32 pixels, 128 threads (4 warps along channels).
__global__ void __launch_bounds__(128) out_gemm_kernel(const float* __restrict__ x,
                                                       float* __restrict__ out) {
    const int px0 = blockIdx.x * 32;
    const int cm0 = blockIdx.y * 128;
    const int b   = blockIdx.z;

    const int tid = threadIdx.x;
    const int w = tid >> 5, lane = tid & 31;
    const int lq = lane >> 2, lr = lane & 3;

    __shared__ __half sW2[128 * 72];
    __shared__ __half sY[32 * 72];

    float acc[2][4][4];
    #pragma unroll
    for (int i = 0; i < 2; ++i)
        #pragma unroll
        for (int j = 0; j < 4; ++j)
            #pragma unroll
            for (int q = 0; q < 4; ++q) acc[i][j][q] = 0.f;

    const __half* Yg = g_yh + ((size_t)b * NPIX + px0) * CIN;

    for (int kc = 0; kc < 4; ++kc) {
        __syncthreads();
        #pragma unroll
        for (int i = tid; i < 1024; i += 128) {
            int m = i >> 3, seg = i & 7;
            *(uint4*)&sW2[m * 72 + seg * 8] =
                *(const uint4*)(g_wouth + (size_t)(cm0 + m) * CIN + kc * 64 + seg * 8);
        }
        #pragma unroll
        for (int i = tid; i < 256; i += 128) {
            int n = i >> 3, seg = i & 7;
            *(uint4*)&sY[n * 72 + seg * 8] =
                *(const uint4*)(Yg + (size_t)n * CIN + kc * 64 + seg * 8);
        }
        __syncthreads();

        #pragma unroll
        for (int ks = 0; ks < 4; ++ks) {
            int kk0 = ks * 16;
            unsigned a[2][4];
            #pragma unroll
            for (int mt = 0; mt < 2; ++mt) {
                int am = w * 32 + mt * 16;
                a[mt][0] = *(unsigned*)&sW2[(am + lq) * 72 + kk0 + lr * 2];
                a[mt][1] = *(unsigned*)&sW2[(am + lq + 8) * 72 + kk0 + lr * 2];
                a[mt][2] = *(unsigned*)&sW2[(am + lq) * 72 + kk0 + lr * 2 + 8];
                a[mt][3] = *(unsigned*)&sW2[(am + lq + 8) * 72 + kk0 + lr * 2 + 8];
            }
            #pragma unroll
            for (int nt = 0; nt < 4; ++nt) {
                int n = nt * 8 + lq;
                unsigned b0 = *(unsigned*)&sY[n * 72 + kk0 + lr * 2];
                unsigned b1 = *(unsigned*)&sY[n * 72 + kk0 + lr * 2 + 8];
                #pragma unroll
                for (int mt = 0; mt < 2; ++mt)
                    mma16816(acc[mt][nt], a[mt][0], a[mt][1], a[mt][2], a[mt][3], b0, b1);
            }
        }
    }

    const float a1c = 0.9191450300180579f;
    const float a2c = 0.3939192985791676f;
    #pragma unroll
    for (int mt = 0; mt < 2; ++mt) {
        #pragma unroll
        for (int nt = 0; nt < 4; ++nt) {
            int ch0 = cm0 + w * 32 + mt * 16 + lq;
            int pix = px0 + nt * 8 + lr * 2;
            #pragma unroll
            for (int rr = 0; rr < 2; ++rr) {
                int ch = ch0 + rr * 8;
                size_t off = ((size_t)b * CIN + ch) * NPIX + pix;
                float2 xv = *(const float2*)&x[off];
                float2 st;
                st.x = a1c * xv.x + a2c * acc[mt][nt][rr * 2 + 0];
                st.y = a1c * xv.y + a2c * acc[mt][nt][rr * 2 + 1];
                *(float2*)&out[off] = st;
            }
        }
    }
}

// ---------------- launch ----------------
extern "C" void kernel_launch(void* const* d_in, const int* in_sizes, int n_in,
                              void* d_out, int out_size) {
    const float* x    = (const float*)d_in[0];
    const float* wqkv = (const float*)d_in[1];
    const float* wout = (const float*)d_in[2];
    float* out = (float*)d_out;

    wnorm_kernel<<<1024, 256>>>(wqkv, wout);
    qkv_fused_kernel<<<dim3(NPIX / 64, 6, BATCH), 256>>>(x);
    attn_mma_kernel<<<dim3(NPIX / 128, NBH, NSPLIT), 128>>>();
    attn_combine_kernel<<<(2 * NBH * NPIX) / 256, 256>>>();
    out_gemm_kernel<<<dim3(NPIX / 32, CIN / 128, BATCH), 128>>>(x, out);
}

// round 14
// speedup vs baseline: 1.0634x; 1.0634x over previous
#include <cuda_runtime.h>
#include <cuda_fp16.h>
#include <math.h>

#define BATCH 2
#define CIN 256
#define NHEADS 8
#define HDIM 32
#define NPIX 4096
#define EPSV 1e-4f
#define NBH (BATCH * NHEADS)
#define NSPLIT 4
#define KT_PER_SPLIT 16
#define PSCL 0.015625f     // 2^-6 partial scale; cancels exactly in sum(O)/sum(l)

#define PADK 40
#define PADV 72
#define PADX 66
#define QSCF (0.17677669529663687f * 1.4426950408889634f)   // 1/sqrt(32) * log2(e)

// ---------------- device scratch ----------------
__device__ __half g_wqkvh[768 * CIN];
__device__ __half g_wouth[CIN * CIN];
__device__ __half g_qh[NBH * NPIX * HDIM];
__device__ __half g_kh[NBH * NPIX * HDIM];
__device__ __half g_vt[NBH * HDIM * NPIX];
__device__ __half g_opart[NSPLIT * NBH * NPIX * HDIM];   // unnormalized O partials * 2^-6 (fp16)
__device__ float  g_lpart[NSPLIT * NBH * NPIX];          // l partials * 2^-6 (fp32)

// ---------------- helpers ----------------
__device__ __forceinline__ void mma16816(float c[4],
                                         unsigned a0, unsigned a1, unsigned a2, unsigned a3,
                                         unsigned b0, unsigned b1) {
    asm volatile(
        "mma.sync.aligned.m16n8k16.row.col.f32.f16.f16.f32 "
        "{%0,%1,%2,%3}, {%4,%5,%6,%7}, {%8,%9}, {%0,%1,%2,%3};"
        : "+f"(c[0]), "+f"(c[1]), "+f"(c[2]), "+f"(c[3])
        : "r"(a0), "r"(a1), "r"(a2), "r"(a3), "r"(b0), "r"(b1));
}

__device__ __forceinline__ void mma16816_f16(unsigned& c0, unsigned& c1,
                                             unsigned a0, unsigned a1, unsigned a2, unsigned a3,
                                             unsigned b0, unsigned b1) {
    asm volatile(
        "mma.sync.aligned.m16n8k16.row.col.f16.f16.f16.f16 "
        "{%0,%1}, {%2,%3,%4,%5}, {%6,%7}, {%0,%1};"
        : "+r"(c0), "+r"(c1)
        : "r"(a0), "r"(a1), "r"(a2), "r"(a3), "r"(b0), "r"(b1));
}

__device__ __forceinline__ unsigned h2exp2(unsigned a) {
    unsigned d;
    asm("ex2.approx.f16x2 %0, %1;" : "=r"(d) : "r"(a));
    return d;
}

__device__ __forceinline__ void ldsm4(unsigned& r0, unsigned& r1, unsigned& r2, unsigned& r3,
                                      unsigned addr) {
    asm volatile("ldmatrix.sync.aligned.m8n8.x4.shared.b16 {%0,%1,%2,%3}, [%4];"
                 : "=r"(r0), "=r"(r1), "=r"(r2), "=r"(r3) : "r"(addr));
}

__device__ __forceinline__ void cpa16(unsigned smem_addr, const void* gptr) {
    asm volatile("cp.async.cg.shared.global [%0], [%1], 16;"
                 :: "r"(smem_addr), "l"(__cvta_generic_to_global(gptr)));
}
__device__ __forceinline__ void cpa_commit() {
    asm volatile("cp.async.commit_group;");
}
__device__ __forceinline__ void cpa_wait0() {
    asm volatile("cp.async.wait_group 0;");
}

// ---------------- kernel 1: weight norm -> fp16 (both weights, one launch) ----------------
__global__ void wnorm_kernel(const float* __restrict__ wqkv, const float* __restrict__ wout) {
    const int r = blockIdx.x;                   // 0..1023
    const int t = threadIdx.x;
    const float* wsrc = (r < 768) ? (wqkv + r * CIN) : (wout + (r - 768) * CIN);
    __half* o = (r < 768) ? (g_wqkvh + r * CIN) : (g_wouth + (r - 768) * CIN);
    float v = wsrc[t];
    __shared__ float red[256];
    red[t] = v * v;
    __syncthreads();
    #pragma unroll
    for (int s = 128; s > 0; s >>= 1) {
        if (t < s) red[t] += red[t + s];
        __syncthreads();
    }
    float n = sqrtf(red[0]);
    float scale = 0.0625f / (EPSV + 0.0625f * n);
    o[t] = __float2half_rn(v * scale);
}

// ---------------- kernel 2: fused QKV HMMA GEMM + pixel-norm (R12 exact) ----------------
__global__ void __launch_bounds__(256) qkv_fused_kernel(const float* __restrict__ x) {
    const int px0 = blockIdx.x * 128;
    const int by  = blockIdx.y;
    const int b   = blockIdx.z;
    const int sec = by >> 1;
    const int cofs = (by & 1) * 128;

    const int tid = threadIdx.x;
    const int w = tid >> 5, lane = tid & 31;
    const int lq = lane >> 2, lr = lane & 3;
    const int wm = w & 3, wn = w >> 2;

    __shared__ __half sX[128 * PADX];
    __shared__ __half sW[128 * 72];

    float acc[2][8][4];
    #pragma unroll
    for (int i = 0; i < 2; ++i)
        #pragma unroll
        for (int j = 0; j < 8; ++j)
            #pragma unroll
            for (int q = 0; q < 4; ++q) acc[i][j][q] = 0.f;

    const float* Xg = x + (size_t)b * CIN * NPIX + px0;
    const __half* Wg = g_wqkvh + (size_t)(sec * 256 + cofs) * CIN;

    for (int kc = 0; kc < 4; ++kc) {
        __syncthreads();
        #pragma unroll
        for (int i = 0; i < 8; ++i) {
            int fidx = tid + i * 256;
            int pix = fidx & 127;
            int c0 = (fidx >> 7) * 4;
            const float* src = Xg + (size_t)(kc * 64 + c0) * NPIX + pix;
            float v0 = src[0];
            float v1 = src[NPIX];
            float v2 = src[2 * NPIX];
            float v3 = src[3 * NPIX];
            *(__half2*)&sX[pix * PADX + c0]     = __floats2half2_rn(v0, v1);
            *(__half2*)&sX[pix * PADX + c0 + 2] = __floats2half2_rn(v2, v3);
        }
        #pragma unroll
        for (int i = tid; i < 1024; i += 256) {
            int n = i >> 3, seg = i & 7;
            *(uint4*)&sW[n * 72 + seg * 8] =
                *(const uint4*)(Wg + (size_t)n * CIN + kc * 64 + seg * 8);
        }
        __syncthreads();

        #pragma unroll
        for (int ks = 0; ks < 4; ++ks) {
            int kk0 = ks * 16;
            unsigned a[2][4];
            #pragma unroll
            for (int mt = 0; mt < 2; ++mt) {
                int am = wm * 32 + mt * 16;
                a[mt][0] = *(unsigned*)&sX[(am + lq) * PADX + kk0 + lr * 2];
                a[mt][1] = *(unsigned*)&sX[(am + lq + 8) * PADX + kk0 + lr * 2];
                a[mt][2] = *(unsigned*)&sX[(am + lq) * PADX + kk0 + lr * 2 + 8];
                a[mt][3] = *(unsigned*)&sX[(am + lq + 8) * PADX + kk0 + lr * 2 + 8];
            }
            #pragma unroll
            for (int nt = 0; nt < 8; ++nt) {
                int n = wn * 64 + nt * 8 + lq;
                unsigned b0 = *(unsigned*)&sW[n * 72 + kk0 + lr * 2];
                unsigned b1 = *(unsigned*)&sW[n * 72 + kk0 + lr * 2 + 8];
                #pragma unroll
                for (int mt = 0; mt < 2; ++mt)
                    mma16816(acc[mt][nt], a[mt][0], a[mt][1], a[mt][2], a[mt][3], b0, b1);
            }
        }
    }

    #pragma unroll
    for (int mt = 0; mt < 2; ++mt) {
        #pragma unroll
        for (int ch = 0; ch < 2; ++ch) {
            float ss0 = 0.f, ss1 = 0.f;
            #pragma unroll
            for (int nt4 = 0; nt4 < 4; ++nt4) {
                int nt = ch * 4 + nt4;
                ss0 += acc[mt][nt][0] * acc[mt][nt][0] + acc[mt][nt][1] * acc[mt][nt][1];
                ss1 += acc[mt][nt][2] * acc[mt][nt][2] + acc[mt][nt][3] * acc[mt][nt][3];
            }
            ss0 += __shfl_xor_sync(0xffffffffu, ss0, 1);
            ss0 += __shfl_xor_sync(0xffffffffu, ss0, 2);
            ss1 += __shfl_xor_sync(0xffffffffu, ss1, 1);
            ss1 += __shfl_xor_sync(0xffffffffu, ss1, 2);
            float sc0 = rsqrtf(ss0 * (1.0f / 32.0f) + EPSV);
            float sc1 = rsqrtf(ss1 * (1.0f / 32.0f) + EPSV);
            if (sec == 0) { sc0 *= QSCF; sc1 *= QSCF; }

            int hh = (cofs >> 5) + wn * 2 + ch;
            int bh = b * NHEADS + hh;
            int pix0r = px0 + wm * 32 + mt * 16 + lq;
            int pix1r = pix0r + 8;

            if (sec == 2) {
                #pragma unroll
                for (int nt4 = 0; nt4 < 4; ++nt4) {
                    int nt = ch * 4 + nt4;
                    int d = nt4 * 8 + lr * 2;
                    __half* base = g_vt + (size_t)bh * HDIM * NPIX;
                    base[(size_t)(d)     * NPIX + pix0r] = __float2half_rn(acc[mt][nt][0] * sc0);
                    base[(size_t)(d + 1) * NPIX + pix0r] = __float2half_rn(acc[mt][nt][1] * sc0);
                    base[(size_t)(d)     * NPIX + pix1r] = __float2half_rn(acc[mt][nt][2] * sc1);
                    base[(size_t)(d + 1) * NPIX + pix1r] = __float2half_rn(acc[mt][nt][3] * sc1);
                }
            } else {
                __half* dst = (sec == 0) ? g_qh : g_kh;
                __half* r0p = dst + ((size_t)bh * NPIX + pix0r) * HDIM;
                __half* r1p = dst + ((size_t)bh * NPIX + pix1r) * HDIM;
                #pragma unroll
                for (int nt4 = 0; nt4 < 4; ++nt4) {
                    int nt = ch * 4 + nt4;
                    int d = nt4 * 8 + lr * 2;
                    *(__half2*)(r0p + d) = __floats2half2_rn(acc[mt][nt][0] * sc0,
                                                             acc[mt][nt][1] * sc0);
                    *(__half2*)(r1p + d) = __floats2half2_rn(acc[mt][nt][2] * sc1,
                                                             acc[mt][nt][3] * sc1);
                }
            }
        }
    }
}

// ---------------- kernel 3: flash attention, split-KV (R12 exact) ----------------
__global__ void __launch_bounds__(128, 4) attn_mma_kernel() {
    const int qb = blockIdx.x;
    const int bh = blockIdx.y;
    const int sp = blockIdx.z;
    const int tid = threadIdx.x;
    const int w = tid >> 5, lane = tid & 31;
    const int lq = lane >> 2, lr = lane & 3;

    const __half* Qg = g_qh + ((size_t)bh * NPIX + qb * 128) * HDIM;
    const __half* Kg = g_kh + ((size_t)bh * NPIX + sp * (KT_PER_SPLIT * 64)) * HDIM;
    const __half* Vg = g_vt + (size_t)bh * HDIM * NPIX + sp * (KT_PER_SPLIT * 64);

    __shared__ __half sQ[128 * PADK];
    __shared__ __half sK[2][64 * PADK];
    __shared__ __half sVt[2][32 * PADV];

    const unsigned sq_u32 = (unsigned)__cvta_generic_to_shared(&sQ[0]);
    const unsigned kbase0 = (unsigned)__cvta_generic_to_shared(&sK[0][0]);
    const unsigned vbase0 = (unsigned)__cvta_generic_to_shared(&sVt[0][0]);
    const unsigned KBUF = 64 * PADK * 2;
    const unsigned VBUF = 32 * PADV * 2;

    #pragma unroll
    for (int i = 0; i < 4; ++i) {
        int idx = tid + i * 128;
        int row = idx >> 2, seg = idx & 3;
        cpa16(sq_u32 + (row * PADK + seg * 8) * 2, Qg + row * 32 + seg * 8);
    }
    #pragma unroll
    for (int i = 0; i < 2; ++i) {
        int s = tid + i * 128;
        int kr = s >> 2, ksg = s & 3;
        cpa16(kbase0 + (kr * PADK + ksg * 8) * 2, Kg + (size_t)kr * 32 + ksg * 8);
        int vr = s >> 3, vsg = s & 7;
        cpa16(vbase0 + (vr * PADV + vsg * 8) * 2, Vg + (size_t)vr * NPIX + vsg * 8);
    }
    cpa_commit();
    cpa_wait0();
    __syncthreads();

    unsigned qf[2][2][4];
    #pragma unroll
    for (int mt = 0; mt < 2; ++mt) {
        int r0 = w * 32 + mt * 16 + lq;
        int r1 = r0 + 8;
        #pragma unroll
        for (int ks = 0; ks < 2; ++ks) {
            qf[mt][ks][0] = *(unsigned*)&sQ[r0 * PADK + ks * 16 + lr * 2];
            qf[mt][ks][1] = *(unsigned*)&sQ[r1 * PADK + ks * 16 + lr * 2];
            qf[mt][ks][2] = *(unsigned*)&sQ[r0 * PADK + ks * 16 + lr * 2 + 8];
            qf[mt][ks][3] = *(unsigned*)&sQ[r1 * PADK + ks * 16 + lr * 2 + 8];
        }
    }

    const unsigned klane = ((lane & 7) * PADK + (lane >> 3) * 8) * 2;
    const unsigned vlane = ((lane & 7) * PADV + (lane >> 3) * 8) * 2;

    float lsum[2][2];
    lsum[0][0] = lsum[0][1] = lsum[1][0] = lsum[1][1] = 0.f;
    float of[2][4][4];
    #pragma unroll
    for (int mt = 0; mt < 2; ++mt)
        #pragma unroll
        for (int nt = 0; nt < 4; ++nt)
            #pragma unroll
            for (int q = 0; q < 4; ++q) of[mt][nt][q] = 0.f;

    for (int kt = 0; kt < KT_PER_SPLIT; ++kt) {
        const int cur = kt & 1;
        const unsigned kb_u32 = kbase0 + cur * KBUF;
        const unsigned vb_u32 = vbase0 + cur * VBUF;

        if (kt < KT_PER_SPLIT - 1) {
            const unsigned kb_n = kbase0 + (cur ^ 1) * KBUF;
            const unsigned vb_n = vbase0 + (cur ^ 1) * VBUF;
            #pragma unroll
            for (int i = 0; i < 2; ++i) {
                int s = tid + i * 128;
                int kr = s >> 2, ksg = s & 3;
                cpa16(kb_n + (kr * PADK + ksg * 8) * 2,
                      Kg + (size_t)((kt + 1) * 64 + kr) * 32 + ksg * 8);
                int vr = s >> 3, vsg = s & 7;
                cpa16(vb_n + (vr * PADV + vsg * 8) * 2,
                      Vg + (size_t)vr * NPIX + (kt + 1) * 64 + vsg * 8);
            }
        }
        cpa_commit();

        unsigned s01[2][8], s23[2][8];
        #pragma unroll
        for (int j = 0; j < 8; ++j) {
            s01[0][j] = s23[0][j] = 0u;
            s01[1][j] = s23[1][j] = 0u;
        }
        #pragma unroll
        for (int j = 0; j < 8; ++j) {
            unsigned kb0, kb1, kb2, kb3;
            ldsm4(kb0, kb1, kb2, kb3, kb_u32 + j * (8 * PADK * 2) + klane);
            mma16816_f16(s01[0][j], s23[0][j], qf[0][0][0], qf[0][0][1], qf[0][0][2], qf[0][0][3], kb0, kb1);
            mma16816_f16(s01[0][j], s23[0][j], qf[0][1][0], qf[0][1][1], qf[0][1][2], qf[0][1][3], kb2, kb3);
            mma16816_f16(s01[1][j], s23[1][j], qf[1][0][0], qf[1][0][1], qf[1][0][2], qf[1][0][3], kb0, kb1);
            mma16816_f16(s01[1][j], s23[1][j], qf[1][1][0], qf[1][1][1], qf[1][1][2], qf[1][1][3], kb2, kb3);
        }

        #pragma unroll
        for (int mt = 0; mt < 2; ++mt) {
            __half2 acc01 = __floats2half2_rn(0.f, 0.f);
            __half2 acc23 = __floats2half2_rn(0.f, 0.f);
            #pragma unroll
            for (int j = 0; j < 8; ++j) {
                s01[mt][j] = h2exp2(s01[mt][j]);
                s23[mt][j] = h2exp2(s23[mt][j]);
                acc01 = __hadd2(acc01, *(__half2*)&s01[mt][j]);
                acc23 = __hadd2(acc23, *(__half2*)&s23[mt][j]);
            }
            lsum[mt][0] += __low2float(acc01) + __high2float(acc01);
            lsum[mt][1] += __low2float(acc23) + __high2float(acc23);
        }

        #pragma unroll
        for (int nt = 0; nt < 4; ++nt) {
            unsigned va0, va1, va2, va3, vb0, vb1, vb2, vb3;
            ldsm4(va0, va1, va2, va3, vb_u32 + nt * (8 * PADV * 2) + vlane);
            ldsm4(vb0, vb1, vb2, vb3, vb_u32 + nt * (8 * PADV * 2) + 64 + vlane);
            #pragma unroll
            for (int mt = 0; mt < 2; ++mt) {
                unsigned od0 = 0u, od1 = 0u;
                mma16816_f16(od0, od1, s01[mt][0], s23[mt][0], s01[mt][1], s23[mt][1], va0, va1);
                mma16816_f16(od0, od1, s01[mt][2], s23[mt][2], s01[mt][3], s23[mt][3], va2, va3);
                mma16816_f16(od0, od1, s01[mt][4], s23[mt][4], s01[mt][5], s23[mt][5], vb0, vb1);
                mma16816_f16(od0, od1, s01[mt][6], s23[mt][6], s01[mt][7], s23[mt][7], vb2, vb3);
                float2 f0 = __half22float2(*(__half2*)&od0);
                float2 f1 = __half22float2(*(__half2*)&od1);
                of[mt][nt][0] += f0.x; of[mt][nt][1] += f0.y;
                of[mt][nt][2] += f1.x; of[mt][nt][3] += f1.y;
            }
        }

        cpa_wait0();
        __syncthreads();
    }

    __half* Obase = g_opart + ((size_t)(sp * NBH + bh) * NPIX + qb * 128) * HDIM;
    float* Lbase = g_lpart + (size_t)(sp * NBH + bh) * NPIX + qb * 128;
    #pragma unroll
    for (int mt = 0; mt < 2; ++mt) {
        float l0 = lsum[mt][0], l1 = lsum[mt][1];
        l0 += __shfl_xor_sync(0xffffffffu, l0, 1);
        l0 += __shfl_xor_sync(0xffffffffu, l0, 2);
        l1 += __shfl_xor_sync(0xffffffffu, l1, 1);
        l1 += __shfl_xor_sync(0xffffffffu, l1, 2);

        int r0 = w * 32 + mt * 16 + lq;
        int r1 = r0 + 8;
        if (lr == 0) {
            Lbase[r0] = l0 * PSCL;
            Lbase[r1] = l1 * PSCL;
        }
        #pragma unroll
        for (int nt = 0; nt < 4; ++nt) {
            int col = nt * 8 + lr * 2;
            *(__half2*)(Obase + (size_t)r0 * HDIM + col) =
                __floats2half2_rn(of[mt][nt][0] * PSCL, of[mt][nt][1] * PSCL);
            *(__half2*)(Obase + (size_t)r1 * HDIM + col) =
                __floats2half2_rn(of[mt][nt][2] * PSCL, of[mt][nt][3] * PSCL);
        }
    }
}

// ---------------- kernel 4: out GEMM HMMA + fused combine + mp_add ----------------
// Block: 64px x 128ch, 256 threads (R12 shape). Y tile is combined on the fly
// from the 4 fp16 O-partials and per-(head,pixel) 1/sum(l).
__global__ void __launch_bounds__(256) out_gemm_kernel(const float* __restrict__ x,
                                                       float* __restrict__ out) {
    const int px0 = blockIdx.x * 64;
    const int cm0 = blockIdx.y * 128;
    const int b   = blockIdx.z;

    const int tid = threadIdx.x;
    const int w = tid >> 5, lane = tid & 31;
    const int lq = lane >> 2, lr = lane & 3;
    const int wm = w & 3, wn = w >> 2;

    __shared__ __half sW2[128 * 72];
    __shared__ __half sY[64 * 72];
    __shared__ float sinvl[8][64];     // [head][pixel-in-tile]

    // precompute 1/sum_sp(l) for all 8 heads x 64 pixels
    #pragma unroll
    for (int i = tid; i < 512; i += 256) {
        int h = i >> 6, n = i & 63;
        int bh = b * NHEADS + h;
        float l = 0.f;
        #pragma unroll
        for (int sp = 0; sp < NSPLIT; ++sp)
            l += g_lpart[(size_t)(sp * NBH + bh) * NPIX + px0 + n];
        sinvl[h][n] = 1.0f / l;
    }

    float acc[2][4][4];
    #pragma unroll
    for (int i = 0; i < 2; ++i)
        #pragma unroll
        for (int j = 0; j < 4; ++j)
            #pragma unroll
            for (int q = 0; q < 4; ++q) acc[i][j][q] = 0.f;

    for (int kc = 0; kc < 4; ++kc) {
        __syncthreads();
        #pragma unroll
        for (int i = tid; i < 1024; i += 256) {
            int m = i >> 3, seg = i & 7;
            *(uint4*)&sW2[m * 72 + seg * 8] =
                *(const uint4*)(g_wouth + (size_t)(cm0 + m) * CIN + kc * 64 + seg * 8);
        }
        // Y tile with fused combine: channels kc*64 .. kc*64+63 = heads 2kc, 2kc+1
        #pragma unroll
        for (int i = tid; i < 512; i += 256) {
            int n = i >> 3, seg = i & 7;          // pixel-in-tile, 8-half segment
            int h = kc * 2 + (seg >> 2);
            int d0 = (seg & 3) * 8;
            int bh = b * NHEADS + h;
            size_t base = ((size_t)bh * NPIX + px0 + n) * HDIM + d0;
            float a[8] = {0.f, 0.f, 0.f, 0.f, 0.f, 0.f, 0.f, 0.f};
            #pragma unroll
            for (int sp = 0; sp < NSPLIT; ++sp) {
                uint4 v = *(const uint4*)(g_opart + (size_t)sp * (NBH * NPIX * HDIM) + base);
                const __half2* h2 = (const __half2*)&v;
                #pragma unroll
                for (int q = 0; q < 4; ++q) {
                    float2 f = __half22float2(h2[q]);
                    a[q * 2]     += f.x;
                    a[q * 2 + 1] += f.y;
                }
            }
            float inv = sinvl[h][n];
            __half2 outv[4];
            #pragma unroll
            for (int q = 0; q < 4; ++q)
                outv[q] = __floats2half2_rn(a[q * 2] * inv, a[q * 2 + 1] * inv);
            *(uint4*)&sY[n * 72 + seg * 8] = *(uint4*)outv;
        }
        __syncthreads();

        #pragma unroll
        for (int ks = 0; ks < 4; ++ks) {
            int kk0 = ks * 16;
            unsigned a[2][4];
            #pragma unroll
            for (int mt = 0; mt < 2; ++mt) {
                int am = wm * 32 + mt * 16;
                a[mt][0] = *(unsigned*)&sW2[(am + lq) * 72 + kk0 + lr * 2];
                a[mt][1] = *(unsigned*)&sW2[(am + lq + 8) * 72 + kk0 + lr * 2];
                a[mt][2] = *(unsigned*)&sW2[(am + lq) * 72 + kk0 + lr * 2 + 8];
                a[mt][3] = *(unsigned*)&sW2[(am + lq + 8) * 72 + kk0 + lr * 2 + 8];
            }
            #pragma unroll
            for (int nt = 0; nt < 4; ++nt) {
                int n = wn * 32 + nt * 8 + lq;
                unsigned b0 = *(unsigned*)&sY[n * 72 + kk0 + lr * 2];
                unsigned b1 = *(unsigned*)&sY[n * 72 + kk0 + lr * 2 + 8];
                #pragma unroll
                for (int mt = 0; mt < 2; ++mt)
                    mma16816(acc[mt][nt], a[mt][0], a[mt][1], a[mt][2], a[mt][3], b0, b1);
            }
        }
    }

    const float a1c = 0.9191450300180579f;
    const float a2c = 0.3939192985791676f;
    #pragma unroll
    for (int mt = 0; mt < 2; ++mt) {
        #pragma unroll
        for (int nt = 0; nt < 4; ++nt) {
            int ch0 = cm0 + wm * 32 + mt * 16 + lq;
            int pix = px0 + wn * 32 + nt * 8 + lr * 2;
            #pragma unroll
            for (int rr = 0; rr < 2; ++rr) {
                int ch = ch0 + rr * 8;
                size_t off = ((size_t)b * CIN + ch) * NPIX + pix;
                float2 xv = *(const float2*)&x[off];
                float2 st;
                st.x = a1c * xv.x + a2c * acc[mt][nt][rr * 2 + 0];
                st.y = a1c * xv.y + a2c * acc[mt][nt][rr * 2 + 1];
                *(float2*)&out[off] = st;
            }
        }
    }
}

// ---------------- launch ----------------
extern "C" void kernel_launch(void* const* d_in, const int* in_sizes, int n_in,
                              void* d_out, int out_size) {
    const float* x    = (const float*)d_in[0];
    const float* wqkv = (const float*)d_in[1];
    const float* wout = (const float*)d_in[2];
    float* out = (float*)d_out;

    wnorm_kernel<<<1024, 256>>>(wqkv, wout);
    qkv_fused_kernel<<<dim3(NPIX / 128, 6, BATCH), 256>>>(x);
    attn_mma_kernel<<<dim3(NPIX / 128, NBH, NSPLIT), 128>>>();
    out_gemm_kernel<<<dim3(NPIX / 64, CIN / 128, BATCH), 256>>>(x, out);
}